// round 6
// baseline (speedup 1.0000x reference)
#include <cuda_runtime.h>
#include <cstdint>

// Problem constants
#define NHEADS 16
#define DHEAD  128
#define SEQ    2048
#define BATCH  4
#define DIM    2048
#define BHTOT  (BATCH * NHEADS)   // 64

// K-dim group-of-8 permutation: stored[j] = natural[p[j]], p=(0,4,1,5,2,6,3,7)
// inv_p = (0,2,4,6,1,3,5,7): natural c stored at (c&~7) | inv_p[c&7].
// Loading float2 at group offset 2*t yields natural (t, t+4) -> exact tf32
// m16n8k8 fragment pair. Numerics identical to unpermuted (same slot mapping).
__device__ __forceinline__ int invp(int c) { return ((c & 3) << 1) | (c >> 2); }

// Scratch (device globals: allocation-free per harness rules)
__device__ float g_Q[(size_t)BHTOT * SEQ * DHEAD];     // [bh][n][dP]  tf32, d permuted
__device__ float g_K[(size_t)BHTOT * SEQ * DHEAD];     // [bh][n][dP]  tf32, d permuted
__device__ float g_V[(size_t)BHTOT * DHEAD * SEQ];     // [bh][d][nP]  tf32, n permuted
__device__ float g_O[(size_t)BATCH * SEQ * DIM];       // [b][n][eP]   tf32, e permuted
__device__ float g_X[(size_t)BATCH * SEQ * DIM];       // tf32, k permuted
__device__ float g_Wqkv[(size_t)3 * DIM * DIM];        // tf32, k permuted
__device__ float g_Wout[(size_t)DIM * DIM];            // tf32, k permuted

// ---------------------------------------------------------------------------
// TF32 / cp.async helpers
// ---------------------------------------------------------------------------
__device__ __forceinline__ uint32_t f2tf32(float f) {
    uint32_t r;
    asm("cvt.rna.tf32.f32 %0, %1;" : "=r"(r) : "f"(f));
    return r;
}
__device__ __forceinline__ float f2tf32f(float f) { return __uint_as_float(f2tf32(f)); }

__device__ __forceinline__ void mma_tf32(float* c, const uint32_t* a, uint32_t b0, uint32_t b1) {
    asm volatile(
        "mma.sync.aligned.m16n8k8.row.col.f32.tf32.tf32.f32 "
        "{%0,%1,%2,%3}, {%4,%5,%6,%7}, {%8,%9}, {%0,%1,%2,%3};\n"
        : "+f"(c[0]), "+f"(c[1]), "+f"(c[2]), "+f"(c[3])
        : "r"(a[0]), "r"(a[1]), "r"(a[2]), "r"(a[3]), "r"(b0), "r"(b1));
}

__device__ __forceinline__ void cp16(float* s, const float* g) {
    uint32_t sa = (uint32_t)__cvta_generic_to_shared(s);
    asm volatile("cp.async.cg.shared.global [%0], [%1], 16;\n" :: "r"(sa), "l"(g));
}
#define CP_COMMIT() asm volatile("cp.async.commit_group;\n" ::: "memory")
#define CP_WAIT1()  asm volatile("cp.async.wait_group 1;\n" ::: "memory")
#define CP_WAIT0()  asm volatile("cp.async.wait_group 0;\n" ::: "memory")

// ---------------------------------------------------------------------------
// Prepass: tf32-round + permute K-dim in groups of 8.
// out group = (n0, n4, n1, n5, n2, n6, n3, n7)
// ---------------------------------------------------------------------------
__global__ __launch_bounds__(256)
void round_perm(const float4* __restrict__ src, float4* __restrict__ dst, int n8)
{
    int i = blockIdx.x * blockDim.x + threadIdx.x;
    if (i < n8) {
        float4 a = src[2 * i], b = src[2 * i + 1];
        dst[2 * i]     = make_float4(f2tf32f(a.x), f2tf32f(b.x), f2tf32f(a.y), f2tf32f(b.y));
        dst[2 * i + 1] = make_float4(f2tf32f(a.z), f2tf32f(b.z), f2tf32f(a.w), f2tf32f(b.w));
    }
}

// ---------------------------------------------------------------------------
// NT GEMM: C[M,N] = A[M,K] * B[N,K]^T, K-permuted operands in HBM.
// Tile 128x128, BK=16, static smem, 2-stage cp.async, 8 warps (4x2).
// Mainloop: LDS.64 fragment loads + MMA only.
// MODE 0: A=g_X, B=g_Wqkv -> scatter g_Q/g_K (d-permuted) / g_V (n-permuted)
// MODE 3: A=g_O (e-permuted), B=g_Wout (k-permuted), +bias -> d_out (natural)
// ---------------------------------------------------------------------------
#define BM 128
#define BN 128
#define BK 16
#define BKP 20

template <int MODE>
__global__ __launch_bounds__(256, 2)
void gemm_nt(const float* __restrict__ bias, float* __restrict__ Cout,
             int M, int N, int K)
{
    __shared__ float As[2][BM * BKP];
    __shared__ float Bs[2][BN * BKP];

    const int tid  = threadIdx.x;
    const int lane = tid & 31;
    const int wid  = tid >> 5;
    const int g    = lane >> 2;
    const int tig  = lane & 3;
    const int wm   = wid & 3;
    const int wn   = wid >> 2;
    const int bm   = blockIdx.y;
    const int bn   = blockIdx.x;

    const float* A = (MODE == 3) ? g_O : g_X;
    const float* B = (MODE == 3) ? g_Wout : g_Wqkv;

    float acc[2][8][4];
    #pragma unroll
    for (int mt = 0; mt < 2; mt++)
        #pragma unroll
        for (int nt = 0; nt < 8; nt++)
            #pragma unroll
            for (int i = 0; i < 4; i++) acc[mt][nt][i] = 0.f;

    const int lrow = tid >> 2;
    const int lcol = (tid & 3) << 2;
    const float* Aptr = A + (size_t)(bm * BM + lrow) * K + lcol;
    const float* Bptr = B + (size_t)(bn * BN + lrow) * K + lcol;

    const int KT = K / BK;

    #pragma unroll
    for (int it = 0; it < 2; it++) {
        cp16(&As[0][(lrow + it * 64) * BKP + lcol], Aptr + (size_t)(it * 64) * K);
        cp16(&Bs[0][(lrow + it * 64) * BKP + lcol], Bptr + (size_t)(it * 64) * K);
    }
    CP_COMMIT();

    for (int kt = 0; kt < KT; kt++) {
        const int cur = kt & 1;
        if (kt + 1 < KT) {
            const int nxt = cur ^ 1;
            const int k1 = (kt + 1) * BK;
            #pragma unroll
            for (int it = 0; it < 2; it++) {
                cp16(&As[nxt][(lrow + it * 64) * BKP + lcol], Aptr + (size_t)(it * 64) * K + k1);
                cp16(&Bs[nxt][(lrow + it * 64) * BKP + lcol], Bptr + (size_t)(it * 64) * K + k1);
            }
            CP_COMMIT();
            CP_WAIT1();
        } else {
            CP_WAIT0();
        }
        __syncthreads();

        #pragma unroll
        for (int ks = 0; ks < 2; ks++) {
            const int kc = ks * 8 + 2 * tig;     // permuted pair offset
            uint32_t afr[2][4];
            #pragma unroll
            for (int mt = 0; mt < 2; mt++) {
                int r0 = wm * 32 + mt * 16 + g;
                float2 lo = *(const float2*)&As[cur][r0 * BKP + kc];
                float2 hi = *(const float2*)&As[cur][(r0 + 8) * BKP + kc];
                afr[mt][0] = __float_as_uint(lo.x);
                afr[mt][1] = __float_as_uint(hi.x);
                afr[mt][2] = __float_as_uint(lo.y);
                afr[mt][3] = __float_as_uint(hi.y);
            }
            #pragma unroll
            for (int nt = 0; nt < 8; nt++) {
                int nr = wn * 64 + nt * 8 + g;
                float2 bp = *(const float2*)&Bs[cur][nr * BKP + kc];
                uint32_t b0 = __float_as_uint(bp.x);
                uint32_t b1 = __float_as_uint(bp.y);
                #pragma unroll
                for (int mt = 0; mt < 2; mt++)
                    mma_tf32(acc[mt][nt], afr[mt], b0, b1);
            }
        }
        __syncthreads();
    }

    const int j0 = invp(2 * tig);       // store position of natural col (..+2*tig)
    const int j1 = invp(2 * tig + 1);   // store position of natural col+1

    #pragma unroll
    for (int mt = 0; mt < 2; mt++) {
        #pragma unroll
        for (int nt = 0; nt < 8; nt++) {
            int row0 = bm * BM + wm * 32 + mt * 16 + g;
            int col  = bn * BN + wn * 64 + nt * 8 + 2 * tig;   // natural, even
            #pragma unroll
            for (int rr = 0; rr < 2; rr++) {
                int row = row0 + rr * 8;
                float x0 = acc[mt][nt][rr * 2 + 0];
                float x1 = acc[mt][nt][rr * 2 + 1];
                if (MODE == 0) {
                    int b = row >> 11, pos = row & 2047;
                    int which = col >> 11, rem = col & 2047;
                    int h = rem >> 7, d = rem & 127;
                    int bhh = (b << 4) + h;
                    int dg = d - 2 * tig;                    // group base (d&~7)
                    if (which == 2) {
                        // V rows = d natural; cols = n permuted (pos&7 == g)
                        int posP = pos - g + invp(g);
                        g_V[((size_t)bhh * DHEAD + d)     * SEQ + posP] = f2tf32f(x0);
                        g_V[((size_t)bhh * DHEAD + d + 1) * SEQ + posP] = f2tf32f(x1);
                    } else if (which == 0) {
                        float* q = g_Q + ((size_t)bhh * SEQ + pos) * DHEAD;
                        q[dg + j0] = x0;
                        q[dg + j1] = x1;
                    } else {
                        float* k = g_K + ((size_t)bhh * SEQ + pos) * DHEAD;
                        k[dg + j0] = x0;
                        k[dg + j1] = x1;
                    }
                } else {
                    // final output: natural layout
                    *(float2*)(Cout + (size_t)row * N + col) =
                        make_float2(x0 + bias[col], x1 + bias[col + 1]);
                }
            }
        }
    }
}

// ---------------------------------------------------------------------------
// RoPE: in-place on g_Q, g_K (d-permuted layout); writes tf32-rounded bits.
// Natural pair (i, i+64): permuted addresses differ by exactly +64.
// ---------------------------------------------------------------------------
__global__ __launch_bounds__(256)
void rope_kernel()
{
    int t = blockIdx.x * blockDim.x + threadIdx.x;   // 64*2048*64 threads
    int i   = t & 63;
    int pos = (t >> 6) & 2047;
    int bh  = t >> 17;
    float p = (float)(2 * i) * (1.0f / 128.0f);
    float inv_freq = powf(10000.0f, -p);
    float fr = (float)pos * inv_freq;
    float s, c;
    sincosf(fr, &s, &c);
    size_t base = ((size_t)bh * SEQ + pos) * DHEAD;
    int dp = (i & ~7) | invp(i & 7);                 // permuted addr of natural i

    float q1 = g_Q[base + dp], q2 = g_Q[base + dp + 64];
    g_Q[base + dp]      = f2tf32f(q1 * c - q2 * s);
    g_Q[base + dp + 64] = f2tf32f(q2 * c + q1 * s);

    float k1 = g_K[base + dp], k2 = g_K[base + dp + 64];
    g_K[base + dp]      = f2tf32f(k1 * c - k2 * s);
    g_K[base + dp + 64] = f2tf32f(k2 * c + k1 * s);
}

// ---------------------------------------------------------------------------
// Fused flash attention. Q/K d-permuted, V n-permuted; P stored n-permuted.
// All fragment loads are LDS.64. O written e-permuted tf32 (feeds gemm<3>).
// ---------------------------------------------------------------------------
#define TKV 64
#define NKVT (SEQ / TKV)     // 32
#define KST 132
#define VST 68
#define FLASH_SMEM_FLOATS (16896 + 17408 + 8704)
#define FLASH_SMEM_BYTES  (FLASH_SMEM_FLOATS * 4)   // 172,032

__global__ __launch_bounds__(256)
void flash_kernel()
{
    extern __shared__ float sm[];
    float* const sK0 = sm;
    float* const sK1 = sm + 8448;
    float* const sV0 = sm + 16896;
    float* const sV1 = sm + 25600;
    float* const sP  = sm + 34304;

    const int tid  = threadIdx.x;
    const int lane = tid & 31;
    const int wid  = tid >> 5;
    const int g    = lane >> 2;
    const int tig  = lane & 3;
    const int bh   = blockIdx.y;
    const int q0   = blockIdx.x * 128;
    const float scale = 0.08838834764831845f;  // 128^-0.5

    const float* Qg = g_Q + (size_t)bh * SEQ * DHEAD;
    const float* Kg = g_K + (size_t)bh * SEQ * DHEAD;
    const float* Vg = g_V + (size_t)bh * DHEAD * SEQ;

    // ---- stage Q tile (128x128, permuted d) through smem ----
    #pragma unroll
    for (int i = 0; i < 16; i++) {
        int e = i * 256 + tid;
        int row = e >> 5, c4 = e & 31;
        cp16(&sm[row * KST + c4 * 4], Qg + (size_t)(q0 + row) * DHEAD + c4 * 4);
    }
    CP_COMMIT();
    CP_WAIT0();
    __syncthreads();

    const int r0 = wid * 16 + g;
    uint32_t qf[16][4];
    #pragma unroll
    for (int kt = 0; kt < 16; kt++) {
        float2 lo = *(const float2*)&sm[r0 * KST + kt * 8 + 2 * tig];
        float2 hi = *(const float2*)&sm[(r0 + 8) * KST + kt * 8 + 2 * tig];
        qf[kt][0] = __float_as_uint(lo.x);
        qf[kt][1] = __float_as_uint(hi.x);
        qf[kt][2] = __float_as_uint(lo.y);
        qf[kt][3] = __float_as_uint(hi.y);
    }
    __syncthreads();

    float oacc[16][4];
    #pragma unroll
    for (int nt = 0; nt < 16; nt++)
        #pragma unroll
        for (int i = 0; i < 4; i++) oacc[nt][i] = 0.f;
    float mrow0 = -1e30f, mrow1 = -1e30f;
    float lrow0 = 0.f, lrow1 = 0.f;

    // prologue: tile 0 into buffer 0
    {
        #pragma unroll
        for (int i = 0; i < 8; i++) {
            int e = i * 256 + tid;
            int kr = e >> 5, kc = e & 31;
            cp16(&sK0[kr * KST + kc * 4], Kg + (size_t)kr * DHEAD + kc * 4);
            int vr = e >> 4, vc = e & 15;
            cp16(&sV0[vr * VST + vc * 4], Vg + (size_t)vr * SEQ + vc * 4);
        }
        CP_COMMIT();
    }

    const int j0 = invp(2 * tig);
    const int j1 = invp(2 * tig + 1);

    for (int it = 0; it < NKVT; it++) {
        const int buf = it & 1;
        const float* sK = buf ? sK1 : sK0;
        const float* sV = buf ? sV1 : sV0;

        if (it + 1 < NKVT) {
            float* dK = buf ? sK0 : sK1;
            float* dV = buf ? sV0 : sV1;
            const int kv1 = (it + 1) * TKV;
            #pragma unroll
            for (int i = 0; i < 8; i++) {
                int e = i * 256 + tid;
                int kr = e >> 5, kc = e & 31;
                cp16(&dK[kr * KST + kc * 4], Kg + (size_t)(kv1 + kr) * DHEAD + kc * 4);
                int vr = e >> 4, vc = e & 15;
                cp16(&dV[vr * VST + vc * 4], Vg + (size_t)vr * SEQ + kv1 + vc * 4);
            }
            CP_COMMIT();
            CP_WAIT1();
        } else {
            CP_WAIT0();
        }
        __syncthreads();

        // ---- S = Q K^T : 16 q rows x 64 kv cols per warp ----
        float sacc[8][4];
        #pragma unroll
        for (int nt = 0; nt < 8; nt++)
            #pragma unroll
            for (int i = 0; i < 4; i++) sacc[nt][i] = 0.f;

        #pragma unroll
        for (int kt = 0; kt < 16; kt++) {
            #pragma unroll
            for (int nt = 0; nt < 8; nt++) {
                float2 bp = *(const float2*)&sK[(nt * 8 + g) * KST + kt * 8 + 2 * tig];
                mma_tf32(sacc[nt], qf[kt], __float_as_uint(bp.x), __float_as_uint(bp.y));
            }
        }

        // ---- online softmax (rows r0, r0+8); cols natural kv ----
        float tm0 = -1e30f, tm1 = -1e30f;
        #pragma unroll
        for (int nt = 0; nt < 8; nt++) {
            tm0 = fmaxf(tm0, fmaxf(sacc[nt][0], sacc[nt][1]));
            tm1 = fmaxf(tm1, fmaxf(sacc[nt][2], sacc[nt][3]));
        }
        tm0 = fmaxf(tm0, __shfl_xor_sync(0xffffffffu, tm0, 1));
        tm0 = fmaxf(tm0, __shfl_xor_sync(0xffffffffu, tm0, 2));
        tm1 = fmaxf(tm1, __shfl_xor_sync(0xffffffffu, tm1, 1));
        tm1 = fmaxf(tm1, __shfl_xor_sync(0xffffffffu, tm1, 2));

        float mn0 = fmaxf(mrow0, tm0 * scale);
        float mn1 = fmaxf(mrow1, tm1 * scale);
        float sf0 = __expf(mrow0 - mn0);
        float sf1 = __expf(mrow1 - mn1);
        mrow0 = mn0; mrow1 = mn1;

        float rs0 = 0.f, rs1 = 0.f;
        #pragma unroll
        for (int nt = 0; nt < 8; nt++) {
            float p0 = __expf(sacc[nt][0] * scale - mn0);
            float p1 = __expf(sacc[nt][1] * scale - mn0);
            float p2 = __expf(sacc[nt][2] * scale - mn1);
            float p3 = __expf(sacc[nt][3] * scale - mn1);
            rs0 += p0 + p1;
            rs1 += p2 + p3;
            // store permuted (match g_V's permuted kv order)
            sP[r0 * VST + nt * 8 + j0]       = f2tf32f(p0);
            sP[r0 * VST + nt * 8 + j1]       = f2tf32f(p1);
            sP[(r0 + 8) * VST + nt * 8 + j0] = f2tf32f(p2);
            sP[(r0 + 8) * VST + nt * 8 + j1] = f2tf32f(p3);
        }
        rs0 += __shfl_xor_sync(0xffffffffu, rs0, 1);
        rs0 += __shfl_xor_sync(0xffffffffu, rs0, 2);
        rs1 += __shfl_xor_sync(0xffffffffu, rs1, 1);
        rs1 += __shfl_xor_sync(0xffffffffu, rs1, 2);
        lrow0 = lrow0 * sf0 + rs0;
        lrow1 = lrow1 * sf1 + rs1;

        #pragma unroll
        for (int nt = 0; nt < 16; nt++) {
            oacc[nt][0] *= sf0;
            oacc[nt][1] *= sf0;
            oacc[nt][2] *= sf1;
            oacc[nt][3] *= sf1;
        }
        __syncthreads();   // sP visible to all

        // ---- O += P V  (both kv-permuted; LDS.64 fragments) ----
        #pragma unroll
        for (int kt = 0; kt < 8; kt++) {
            uint32_t afr[4];
            {
                float2 lo = *(const float2*)&sP[r0 * VST + kt * 8 + 2 * tig];
                float2 hi = *(const float2*)&sP[(r0 + 8) * VST + kt * 8 + 2 * tig];
                afr[0] = __float_as_uint(lo.x);
                afr[1] = __float_as_uint(hi.x);
                afr[2] = __float_as_uint(lo.y);
                afr[3] = __float_as_uint(hi.y);
            }
            #pragma unroll
            for (int nt = 0; nt < 16; nt++) {
                float2 bp = *(const float2*)&sV[(nt * 8 + g) * VST + kt * 8 + 2 * tig];
                mma_tf32(oacc[nt], afr, __float_as_uint(bp.x), __float_as_uint(bp.y));
            }
        }
        __syncthreads();
    }

    // ---- epilogue: normalize, round tf32, write e-permuted g_O ----
    float inv0 = 1.f / lrow0;
    float inv1 = 1.f / lrow1;
    int b = bh >> 4, h = bh & 15;
    float* Og = g_O + ((size_t)(b * SEQ + q0)) * DIM + h * DHEAD;
    #pragma unroll
    for (int nt = 0; nt < 16; nt++) {
        Og[(size_t)r0 * DIM + nt * 8 + j0] = f2tf32f(oacc[nt][0] * inv0);
        Og[(size_t)r0 * DIM + nt * 8 + j1] = f2tf32f(oacc[nt][1] * inv0);
        Og[(size_t)(r0 + 8) * DIM + nt * 8 + j0] = f2tf32f(oacc[nt][2] * inv1);
        Og[(size_t)(r0 + 8) * DIM + nt * 8 + j1] = f2tf32f(oacc[nt][3] * inv1);
    }
}

// ---------------------------------------------------------------------------
// Launch: metadata order = x, w_qkv, w_out, b_out ; output fp32 [4,2048,2048]
// ---------------------------------------------------------------------------
extern "C" void kernel_launch(void* const* d_in, const int* in_sizes, int n_in,
                              void* d_out, int out_size)
{
    const float* x     = (const float*)d_in[0];
    const float* w_qkv = (const float*)d_in[1];
    const float* w_out = (const float*)d_in[2];
    const float* b_out = (const float*)d_in[3];
    float* out = (float*)d_out;

    static bool attr_set = false;
    if (!attr_set) {
        cudaFuncSetAttribute(flash_kernel,
                             cudaFuncAttributeMaxDynamicSharedMemorySize,
                             FLASH_SMEM_BYTES);
        attr_set = true;
    }

    float* gx; float* gwq; float* gwo;
    cudaGetSymbolAddress((void**)&gx,  g_X);
    cudaGetSymbolAddress((void**)&gwq, g_Wqkv);
    cudaGetSymbolAddress((void**)&gwo, g_Wout);

    // Prepass: tf32-round + K-group permute inputs.
    const int n8x = (BATCH * SEQ * DIM) / 8;          // 2,097,152
    const int n8q = (3 * DIM * DIM) / 8;              // 1,572,864
    const int n8o = (DIM * DIM) / 8;                  // 524,288
    round_perm<<<(n8x + 255) / 256, 256>>>((const float4*)x,     (float4*)gx,  n8x);
    round_perm<<<(n8q + 255) / 256, 256>>>((const float4*)w_qkv, (float4*)gwq, n8q);
    round_perm<<<(n8o + 255) / 256, 256>>>((const float4*)w_out, (float4*)gwo, n8o);

    // QKV projection: [8192,2048] x [6144,2048]^T, scatter to Q/K/V layouts
    gemm_nt<0><<<dim3(48, 64, 1), 256>>>(nullptr, nullptr, 8192, 6144, 2048);
    // RoPE in place on Q, K (permuted d addressing, tf32-rounded)
    rope_kernel<<<(BHTOT * SEQ * 64) / 256, 256>>>();
    // Fused attention -> g_O (tf32, e-permuted)
    flash_kernel<<<dim3(16, 64, 1), 256, FLASH_SMEM_BYTES>>>();
    // Output projection + bias: [8192,2048] x [2048,2048]^T -> natural output
    gemm_nt<3><<<dim3(16, 64, 1), 256>>>(b_out, out, 8192, DIM, DIM);
}

// round 7
// speedup vs baseline: 1.3193x; 1.3193x over previous
#include <cuda_runtime.h>
#include <cstdint>

// Problem constants
#define NHEADS 16
#define DHEAD  128
#define SEQ    2048
#define BATCH  4
#define DIM    2048
#define BHTOT  (BATCH * NHEADS)   // 64

// Scratch (device globals: allocation-free per harness rules)
__device__ float g_Q[(size_t)BHTOT * SEQ * DHEAD];     // [bh][n][d]  tf32 (after rope)
__device__ float g_K[(size_t)BHTOT * SEQ * DHEAD];     // [bh][n][d]  tf32 (after rope)
__device__ float g_V[(size_t)BHTOT * DHEAD * SEQ];     // [bh][d][n]  tf32, transposed
__device__ float g_O[(size_t)BATCH * SEQ * DIM];       // [b][n][h*d] tf32 (flash rounds)
__device__ float g_X[(size_t)BATCH * SEQ * DIM];       // tf32 copy of x
__device__ float g_Wqkv[(size_t)3 * DIM * DIM];        // tf32 copy of w_qkv
__device__ float g_Wout[(size_t)DIM * DIM];            // tf32 copy of w_out

// ---------------------------------------------------------------------------
// TF32 / cp.async helpers
// ---------------------------------------------------------------------------
__device__ __forceinline__ uint32_t f2tf32(float f) {
    uint32_t r;
    asm("cvt.rna.tf32.f32 %0, %1;" : "=r"(r) : "f"(f));
    return r;
}
__device__ __forceinline__ float f2tf32f(float f) { return __uint_as_float(f2tf32(f)); }

__device__ __forceinline__ void mma_tf32(float* c, const uint32_t* a, uint32_t b0, uint32_t b1) {
    asm volatile(
        "mma.sync.aligned.m16n8k8.row.col.f32.tf32.tf32.f32 "
        "{%0,%1,%2,%3}, {%4,%5,%6,%7}, {%8,%9}, {%0,%1,%2,%3};\n"
        : "+f"(c[0]), "+f"(c[1]), "+f"(c[2]), "+f"(c[3])
        : "r"(a[0]), "r"(a[1]), "r"(a[2]), "r"(a[3]), "r"(b0), "r"(b1));
}

__device__ __forceinline__ void cp16(float* s, const float* g) {
    uint32_t sa = (uint32_t)__cvta_generic_to_shared(s);
    asm volatile("cp.async.cg.shared.global [%0], [%1], 16;\n" :: "r"(sa), "l"(g));
}
#define CP_COMMIT() asm volatile("cp.async.commit_group;\n" ::: "memory")
#define CP_WAIT1()  asm volatile("cp.async.wait_group 1;\n" ::: "memory")
#define CP_WAIT0()  asm volatile("cp.async.wait_group 0;\n" ::: "memory")

// ---------------------------------------------------------------------------
// Prepass: round fp32 -> tf32 bits, elementwise copy (float4).
// ---------------------------------------------------------------------------
__global__ __launch_bounds__(256)
void round_copy(const float4* __restrict__ src, float4* __restrict__ dst, int n4)
{
    int i = blockIdx.x * blockDim.x + threadIdx.x;
    if (i < n4) {
        float4 v = src[i];
        v.x = f2tf32f(v.x); v.y = f2tf32f(v.y);
        v.z = f2tf32f(v.z); v.w = f2tf32f(v.w);
        dst[i] = v;
    }
}

// ---------------------------------------------------------------------------
// NT GEMM: C[M,N] = A[M,K] * B[N,K]^T  (row-major, K contiguous).
// Tile 128x128, BK=16, THREE-stage cp.async ring (dynamic smem, 60 KB):
// the stage being written is always 2 ahead of the one being read, so one
// __syncthreads per chunk suffices (it both publishes stage kt and retires
// all reads of the buffer about to be overwritten).
// All operands pre-rounded tf32 in HBM -> mainloop is scalar LDS + MMA only
// (scalar 32-bit LDS is conflict-free at BKP=20; R6 showed LDS.64 is not).
// 8 warps (4 along M x 2 along N), warp 32x64 via 2x8 m16n8k8 TF32 tiles.
// MODE 0: A=g_X, B=g_Wqkv -> scatter g_Q / g_K (raw; rope rounds) / g_V (tf32)
// MODE 3: A=g_O (tf32), B=g_Wout (tf32), +bias -> d_out
// ---------------------------------------------------------------------------
#define BM 128
#define BN 128
#define BK 16
#define BKP 20
#define NSTAGE 3
#define STAGE_FLOATS (2 * BM * BKP)                    // A + B per stage
#define GEMM_SMEM_BYTES (NSTAGE * STAGE_FLOATS * 4)    // 61,440

template <int MODE>
__global__ __launch_bounds__(256, 2)
void gemm_nt(const float* __restrict__ bias, float* __restrict__ Cout,
             int M, int N, int K)
{
    extern __shared__ float sg[];

    const int tid  = threadIdx.x;
    const int lane = tid & 31;
    const int wid  = tid >> 5;
    const int g    = lane >> 2;
    const int tig  = lane & 3;
    const int wm   = wid & 3;
    const int wn   = wid >> 2;
    const int bm   = blockIdx.y;
    const int bn   = blockIdx.x;

    const float* A = (MODE == 3) ? g_O : g_X;
    const float* B = (MODE == 3) ? g_Wout : g_Wqkv;

    float acc[2][8][4];
    #pragma unroll
    for (int mt = 0; mt < 2; mt++)
        #pragma unroll
        for (int nt = 0; nt < 8; nt++)
            #pragma unroll
            for (int i = 0; i < 4; i++) acc[mt][nt][i] = 0.f;

    const int lrow = tid >> 2;          // 0..63
    const int lcol = (tid & 3) << 2;    // 0,4,8,12
    const float* Aptr = A + (size_t)(bm * BM + lrow) * K + lcol;
    const float* Bptr = B + (size_t)(bn * BN + lrow) * K + lcol;

    const int KT = K / BK;

    // prologue: stages 0 and 1
    #pragma unroll
    for (int s = 0; s < 2; s++) {
        float* As = sg + s * STAGE_FLOATS;
        float* Bs = As + BM * BKP;
        const int k0 = s * BK;
        #pragma unroll
        for (int it = 0; it < 2; it++) {
            cp16(&As[(lrow + it * 64) * BKP + lcol], Aptr + (size_t)(it * 64) * K + k0);
            cp16(&Bs[(lrow + it * 64) * BKP + lcol], Bptr + (size_t)(it * 64) * K + k0);
        }
        CP_COMMIT();
    }

    int rbuf = 0;                       // stage holding chunk kt
    for (int kt = 0; kt < KT; kt++) {
        if (kt + 1 < KT) { CP_WAIT1(); } else { CP_WAIT0(); }
        __syncthreads();                // publish stage kt; retire reads of wbuf

        if (kt + 2 < KT) {
            int wbuf = rbuf + 2; if (wbuf >= NSTAGE) wbuf -= NSTAGE;
            float* As = sg + wbuf * STAGE_FLOATS;
            float* Bs = As + BM * BKP;
            const int k2 = (kt + 2) * BK;
            #pragma unroll
            for (int it = 0; it < 2; it++) {
                cp16(&As[(lrow + it * 64) * BKP + lcol], Aptr + (size_t)(it * 64) * K + k2);
                cp16(&Bs[(lrow + it * 64) * BKP + lcol], Bptr + (size_t)(it * 64) * K + k2);
            }
            CP_COMMIT();
        }

        const float* As = sg + rbuf * STAGE_FLOATS;
        const float* Bs = As + BM * BKP;
        #pragma unroll
        for (int ks = 0; ks < 2; ks++) {
            uint32_t afr[2][4];
            #pragma unroll
            for (int mt = 0; mt < 2; mt++) {
                int r0 = wm * 32 + mt * 16 + g;
                int c0 = ks * 8 + tig;
                afr[mt][0] = __float_as_uint(As[r0 * BKP + c0]);
                afr[mt][1] = __float_as_uint(As[(r0 + 8) * BKP + c0]);
                afr[mt][2] = __float_as_uint(As[r0 * BKP + c0 + 4]);
                afr[mt][3] = __float_as_uint(As[(r0 + 8) * BKP + c0 + 4]);
            }
            #pragma unroll
            for (int nt = 0; nt < 8; nt++) {
                int nr = wn * 64 + nt * 8 + g;
                int kc = ks * 8 + tig;
                uint32_t b0 = __float_as_uint(Bs[nr * BKP + kc]);
                uint32_t b1 = __float_as_uint(Bs[nr * BKP + kc + 4]);
                #pragma unroll
                for (int mt = 0; mt < 2; mt++)
                    mma_tf32(acc[mt][nt], afr[mt], b0, b1);
            }
        }

        if (++rbuf == NSTAGE) rbuf = 0;
    }

    #pragma unroll
    for (int mt = 0; mt < 2; mt++) {
        #pragma unroll
        for (int nt = 0; nt < 8; nt++) {
            int row0 = bm * BM + wm * 32 + mt * 16 + g;
            int col  = bn * BN + wn * 64 + nt * 8 + 2 * tig;
            #pragma unroll
            for (int rr = 0; rr < 2; rr++) {
                int row = row0 + rr * 8;
                float x0 = acc[mt][nt][rr * 2 + 0];
                float x1 = acc[mt][nt][rr * 2 + 1];
                if (MODE == 0) {
                    int b = row >> 11, pos = row & 2047;
                    int which = col >> 11, rem = col & 2047;
                    int h = rem >> 7, d = rem & 127;
                    int bhh = (b << 4) + h;
                    if (which == 2) {
                        // V: pre-round so flash mainloop is CVT-free
                        g_V[((size_t)bhh * DHEAD + d)     * SEQ + pos] = f2tf32f(x0);
                        g_V[((size_t)bhh * DHEAD + d + 1) * SEQ + pos] = f2tf32f(x1);
                    } else if (which == 0) {
                        *(float2*)(g_Q + ((size_t)bhh * SEQ + pos) * DHEAD + d) = make_float2(x0, x1);
                    } else {
                        *(float2*)(g_K + ((size_t)bhh * SEQ + pos) * DHEAD + d) = make_float2(x0, x1);
                    }
                } else {
                    *(float2*)(Cout + (size_t)row * N + col) =
                        make_float2(x0 + bias[col], x1 + bias[col + 1]);
                }
            }
        }
    }
}

// ---------------------------------------------------------------------------
// RoPE: in-place on g_Q, g_K; writes tf32-rounded bits.
// ---------------------------------------------------------------------------
__global__ __launch_bounds__(256)
void rope_kernel()
{
    int t = blockIdx.x * blockDim.x + threadIdx.x;   // 64*2048*64 threads
    int i   = t & 63;
    int pos = (t >> 6) & 2047;
    int bh  = t >> 17;
    float p = (float)(2 * i) * (1.0f / 128.0f);
    float inv_freq = powf(10000.0f, -p);
    float fr = (float)pos * inv_freq;
    float s, c;
    sincosf(fr, &s, &c);
    size_t base = ((size_t)bh * SEQ + pos) * DHEAD;

    float q1 = g_Q[base + i], q2 = g_Q[base + i + 64];
    g_Q[base + i]      = f2tf32f(q1 * c - q2 * s);
    g_Q[base + i + 64] = f2tf32f(q2 * c + q1 * s);

    float k1 = g_K[base + i], k2 = g_K[base + i + 64];
    g_K[base + i]      = f2tf32f(k1 * c - k2 * s);
    g_K[base + i + 64] = f2tf32f(k2 * c + k1 * s);
}

// ---------------------------------------------------------------------------
// Fused flash attention: per block = (q-tile of 128 rows, bh).
// 8 warps x 16 q-rows; row reductions are shfl.bfly within 4-lane groups.
// Q register-resident; K/V/Q pre-rounded tf32 in HBM -> mainloop raw LDS+MMA.
// K/V double-buffered cp.async. P tf32-pre-rounded through smem.
// Epilogue writes g_O tf32-rounded (feeds gemm<3> raw).
// ---------------------------------------------------------------------------
#define TKV 64
#define NKVT (SEQ / TKV)     // 32
#define KST 132
#define VST 68
#define FLASH_SMEM_FLOATS (16896 + 17408 + 8704)
#define FLASH_SMEM_BYTES  (FLASH_SMEM_FLOATS * 4)   // 172,032

__global__ __launch_bounds__(256)
void flash_kernel()
{
    extern __shared__ float sm[];
    float* const sK0 = sm;
    float* const sK1 = sm + 8448;
    float* const sV0 = sm + 16896;
    float* const sV1 = sm + 25600;
    float* const sP  = sm + 34304;

    const int tid  = threadIdx.x;
    const int lane = tid & 31;
    const int wid  = tid >> 5;
    const int g    = lane >> 2;
    const int tig  = lane & 3;
    const int bh   = blockIdx.y;
    const int q0   = blockIdx.x * 128;
    const float scale = 0.08838834764831845f;  // 128^-0.5

    const float* Qg = g_Q + (size_t)bh * SEQ * DHEAD;
    const float* Kg = g_K + (size_t)bh * SEQ * DHEAD;
    const float* Vg = g_V + (size_t)bh * DHEAD * SEQ;

    // ---- stage Q tile (128x128) through smem, extract A-fragments ----
    #pragma unroll
    for (int i = 0; i < 16; i++) {
        int e = i * 256 + tid;
        int row = e >> 5, c4 = e & 31;
        cp16(&sm[row * KST + c4 * 4], Qg + (size_t)(q0 + row) * DHEAD + c4 * 4);
    }
    CP_COMMIT();
    CP_WAIT0();
    __syncthreads();

    const int r0 = wid * 16 + g;
    uint32_t qf[16][4];
    #pragma unroll
    for (int kt = 0; kt < 16; kt++) {
        qf[kt][0] = __float_as_uint(sm[r0 * KST + kt * 8 + tig]);
        qf[kt][1] = __float_as_uint(sm[(r0 + 8) * KST + kt * 8 + tig]);
        qf[kt][2] = __float_as_uint(sm[r0 * KST + kt * 8 + tig + 4]);
        qf[kt][3] = __float_as_uint(sm[(r0 + 8) * KST + kt * 8 + tig + 4]);
    }
    __syncthreads();

    float oacc[16][4];
    #pragma unroll
    for (int nt = 0; nt < 16; nt++)
        #pragma unroll
        for (int i = 0; i < 4; i++) oacc[nt][i] = 0.f;
    float mrow0 = -1e30f, mrow1 = -1e30f;
    float lrow0 = 0.f, lrow1 = 0.f;

    // prologue: tile 0 into buffer 0
    {
        #pragma unroll
        for (int i = 0; i < 8; i++) {
            int e = i * 256 + tid;
            int kr = e >> 5, kc = e & 31;
            cp16(&sK0[kr * KST + kc * 4], Kg + (size_t)kr * DHEAD + kc * 4);
            int vr = e >> 4, vc = e & 15;
            cp16(&sV0[vr * VST + vc * 4], Vg + (size_t)vr * SEQ + vc * 4);
        }
        CP_COMMIT();
    }

    for (int it = 0; it < NKVT; it++) {
        const int buf = it & 1;
        const float* sK = buf ? sK1 : sK0;
        const float* sV = buf ? sV1 : sV0;

        if (it + 1 < NKVT) {
            float* dK = buf ? sK0 : sK1;
            float* dV = buf ? sV0 : sV1;
            const int kv1 = (it + 1) * TKV;
            #pragma unroll
            for (int i = 0; i < 8; i++) {
                int e = i * 256 + tid;
                int kr = e >> 5, kc = e & 31;
                cp16(&dK[kr * KST + kc * 4], Kg + (size_t)(kv1 + kr) * DHEAD + kc * 4);
                int vr = e >> 4, vc = e & 15;
                cp16(&dV[vr * VST + vc * 4], Vg + (size_t)vr * SEQ + kv1 + vc * 4);
            }
            CP_COMMIT();
            CP_WAIT1();
        } else {
            CP_WAIT0();
        }
        __syncthreads();

        // ---- S = Q K^T for this warp's 16 rows x 64 kv cols ----
        float sacc[8][4];
        #pragma unroll
        for (int nt = 0; nt < 8; nt++)
            #pragma unroll
            for (int i = 0; i < 4; i++) sacc[nt][i] = 0.f;

        #pragma unroll
        for (int kt = 0; kt < 16; kt++) {
            #pragma unroll
            for (int nt = 0; nt < 8; nt++) {
                uint32_t b0 = __float_as_uint(sK[(nt * 8 + g) * KST + kt * 8 + tig]);
                uint32_t b1 = __float_as_uint(sK[(nt * 8 + g) * KST + kt * 8 + tig + 4]);
                mma_tf32(sacc[nt], qf[kt], b0, b1);
            }
        }

        // ---- online softmax (rows r0 and r0+8) ----
        float tm0 = -1e30f, tm1 = -1e30f;
        #pragma unroll
        for (int nt = 0; nt < 8; nt++) {
            tm0 = fmaxf(tm0, fmaxf(sacc[nt][0], sacc[nt][1]));
            tm1 = fmaxf(tm1, fmaxf(sacc[nt][2], sacc[nt][3]));
        }
        tm0 = fmaxf(tm0, __shfl_xor_sync(0xffffffffu, tm0, 1));
        tm0 = fmaxf(tm0, __shfl_xor_sync(0xffffffffu, tm0, 2));
        tm1 = fmaxf(tm1, __shfl_xor_sync(0xffffffffu, tm1, 1));
        tm1 = fmaxf(tm1, __shfl_xor_sync(0xffffffffu, tm1, 2));

        float mn0 = fmaxf(mrow0, tm0 * scale);
        float mn1 = fmaxf(mrow1, tm1 * scale);
        float sf0 = __expf(mrow0 - mn0);
        float sf1 = __expf(mrow1 - mn1);
        mrow0 = mn0; mrow1 = mn1;

        float rs0 = 0.f, rs1 = 0.f;
        #pragma unroll
        for (int nt = 0; nt < 8; nt++) {
            float p0 = __expf(sacc[nt][0] * scale - mn0);
            float p1 = __expf(sacc[nt][1] * scale - mn0);
            float p2 = __expf(sacc[nt][2] * scale - mn1);
            float p3 = __expf(sacc[nt][3] * scale - mn1);
            rs0 += p0 + p1;
            rs1 += p2 + p3;
            *(float2*)&sP[r0 * VST + nt * 8 + 2 * tig] =
                make_float2(f2tf32f(p0), f2tf32f(p1));
            *(float2*)&sP[(r0 + 8) * VST + nt * 8 + 2 * tig] =
                make_float2(f2tf32f(p2), f2tf32f(p3));
        }
        rs0 += __shfl_xor_sync(0xffffffffu, rs0, 1);
        rs0 += __shfl_xor_sync(0xffffffffu, rs0, 2);
        rs1 += __shfl_xor_sync(0xffffffffu, rs1, 1);
        rs1 += __shfl_xor_sync(0xffffffffu, rs1, 2);
        lrow0 = lrow0 * sf0 + rs0;
        lrow1 = lrow1 * sf1 + rs1;

        #pragma unroll
        for (int nt = 0; nt < 16; nt++) {
            oacc[nt][0] *= sf0;
            oacc[nt][1] *= sf0;
            oacc[nt][2] *= sf1;
            oacc[nt][3] *= sf1;
        }
        __syncthreads();   // sP visible to all

        // ---- O += P V ----
        #pragma unroll
        for (int kt = 0; kt < 8; kt++) {
            uint32_t afr[4];
            afr[0] = __float_as_uint(sP[r0 * VST + kt * 8 + tig]);
            afr[1] = __float_as_uint(sP[(r0 + 8) * VST + kt * 8 + tig]);
            afr[2] = __float_as_uint(sP[r0 * VST + kt * 8 + tig + 4]);
            afr[3] = __float_as_uint(sP[(r0 + 8) * VST + kt * 8 + tig + 4]);
            #pragma unroll
            for (int nt = 0; nt < 16; nt++) {
                uint32_t b0 = __float_as_uint(sV[(nt * 8 + g) * VST + kt * 8 + tig]);
                uint32_t b1 = __float_as_uint(sV[(nt * 8 + g) * VST + kt * 8 + tig + 4]);
                mma_tf32(oacc[nt], afr, b0, b1);
            }
        }
        __syncthreads();   // all reads of sK/sV/sP done before next overwrite
    }

    // ---- epilogue: normalize, round to tf32 (feeds gemm<3> raw), write ----
    float inv0 = 1.f / lrow0;
    float inv1 = 1.f / lrow1;
    int b = bh >> 4, h = bh & 15;
    float* Og = g_O + ((size_t)(b * SEQ + q0)) * DIM + h * DHEAD;
    #pragma unroll
    for (int nt = 0; nt < 16; nt++) {
        int col = nt * 8 + 2 * tig;
        *(float2*)(Og + (size_t)r0 * DIM + col) =
            make_float2(f2tf32f(oacc[nt][0] * inv0), f2tf32f(oacc[nt][1] * inv0));
        *(float2*)(Og + (size_t)(r0 + 8) * DIM + col) =
            make_float2(f2tf32f(oacc[nt][2] * inv1), f2tf32f(oacc[nt][3] * inv1));
    }
}

// ---------------------------------------------------------------------------
// Launch: metadata order = x, w_qkv, w_out, b_out ; output fp32 [4,2048,2048]
// ---------------------------------------------------------------------------
extern "C" void kernel_launch(void* const* d_in, const int* in_sizes, int n_in,
                              void* d_out, int out_size)
{
    const float* x     = (const float*)d_in[0];
    const float* w_qkv = (const float*)d_in[1];
    const float* w_out = (const float*)d_in[2];
    const float* b_out = (const float*)d_in[3];
    float* out = (float*)d_out;

    static bool attr_set = false;
    if (!attr_set) {
        cudaFuncSetAttribute(flash_kernel,
                             cudaFuncAttributeMaxDynamicSharedMemorySize,
                             FLASH_SMEM_BYTES);
        cudaFuncSetAttribute(gemm_nt<0>,
                             cudaFuncAttributeMaxDynamicSharedMemorySize,
                             GEMM_SMEM_BYTES);
        cudaFuncSetAttribute(gemm_nt<3>,
                             cudaFuncAttributeMaxDynamicSharedMemorySize,
                             GEMM_SMEM_BYTES);
        attr_set = true;
    }

    float* gx; float* gwq; float* gwo;
    cudaGetSymbolAddress((void**)&gx,  g_X);
    cudaGetSymbolAddress((void**)&gwq, g_Wqkv);
    cudaGetSymbolAddress((void**)&gwo, g_Wout);

    // Prepass: tf32-round inputs into device globals (single rounding point).
    const int n4x = (BATCH * SEQ * DIM) / 4;          // 4,194,304
    const int n4q = (3 * DIM * DIM) / 4;              // 3,145,728
    const int n4o = (DIM * DIM) / 4;                  // 1,048,576
    round_copy<<<(n4x + 255) / 256, 256>>>((const float4*)x,     (float4*)gx,  n4x);
    round_copy<<<(n4q + 255) / 256, 256>>>((const float4*)w_qkv, (float4*)gwq, n4q);
    round_copy<<<(n4o + 255) / 256, 256>>>((const float4*)w_out, (float4*)gwo, n4o);

    // QKV projection: [8192,2048] x [6144,2048]^T, scatter to Q/K/V layouts
    gemm_nt<0><<<dim3(48, 64, 1), 256, GEMM_SMEM_BYTES>>>(nullptr, nullptr, 8192, 6144, 2048);
    // RoPE in place on Q, K (writes tf32-rounded)
    rope_kernel<<<(BHTOT * SEQ * 64) / 256, 256>>>();
    // Fused attention -> g_O (tf32-rounded)
    flash_kernel<<<dim3(16, 64, 1), 256, FLASH_SMEM_BYTES>>>();
    // Output projection + bias: [8192,2048] x [2048,2048]^T
    gemm_nt<3><<<dim3(16, 64, 1), 256, GEMM_SMEM_BYTES>>>(b_out, out, 8192, DIM, DIM);
}

// round 11
// speedup vs baseline: 2.4548x; 1.8607x over previous
#include <cuda_runtime.h>
#include <cuda_fp16.h>
#include <cstdint>

// Problem constants
#define NHEADS 16
#define DHEAD  128
#define SEQ    2048
#define BATCH  4
#define DIM    2048
#define BHTOT  (BATCH * NHEADS)   // 64

// NOTE (R9 lesson): harness compiles with -arch=sm_100 (no 'a' suffix) —
// tcgen05/TMEM are NOT available. Legacy mma.sync only.

// Scratch (device globals: allocation-free per harness rules) — fp16 operands
__device__ __half g_Q[(size_t)BHTOT * SEQ * DHEAD];     // [bh][n][d]
__device__ __half g_K[(size_t)BHTOT * SEQ * DHEAD];     // [bh][n][d]
__device__ __half g_V[(size_t)BHTOT * DHEAD * SEQ];     // [bh][d][n] transposed
__device__ __half g_O[(size_t)BATCH * SEQ * DIM];       // [b][n][h*d]
__device__ __half g_X[(size_t)BATCH * SEQ * DIM];       // fp16 copy of x
__device__ __half g_Wqkv[(size_t)3 * DIM * DIM];        // fp16 copy of w_qkv
__device__ __half g_Wout[(size_t)DIM * DIM];            // fp16 copy of w_out

// ---------------------------------------------------------------------------
// Helpers
// ---------------------------------------------------------------------------
__device__ __forceinline__ void mma_f16(float* c, const uint32_t* a, uint32_t b0, uint32_t b1) {
    asm volatile(
        "mma.sync.aligned.m16n8k16.row.col.f32.f16.f16.f32 "
        "{%0,%1,%2,%3}, {%4,%5,%6,%7}, {%8,%9}, {%0,%1,%2,%3};\n"
        : "+f"(c[0]), "+f"(c[1]), "+f"(c[2]), "+f"(c[3])
        : "r"(a[0]), "r"(a[1]), "r"(a[2]), "r"(a[3]), "r"(b0), "r"(b1));
}

__device__ __forceinline__ void cp16s(uint32_t sa, const void* g) {
    asm volatile("cp.async.cg.shared.global [%0], [%1], 16;\n" :: "r"(sa), "l"(g));
}
#define CP_COMMIT() asm volatile("cp.async.commit_group;\n" ::: "memory")
#define CP_WAIT1()  asm volatile("cp.async.wait_group 1;\n" ::: "memory")
#define CP_WAIT0()  asm volatile("cp.async.wait_group 0;\n" ::: "memory")

__device__ __forceinline__ uint32_t h2u(__half2 h) { return *(uint32_t*)&h; }

// ---------------------------------------------------------------------------
// Prepass: fp32 -> fp16 (RN), float4 -> 4 halves (uint2).
// ---------------------------------------------------------------------------
__global__ __launch_bounds__(256)
void round_half(const float4* __restrict__ src, uint2* __restrict__ dst, int n4)
{
    int i = blockIdx.x * blockDim.x + threadIdx.x;
    if (i < n4) {
        float4 v = src[i];
        __half2 a = __floats2half2_rn(v.x, v.y);
        __half2 b = __floats2half2_rn(v.z, v.w);
        dst[i] = make_uint2(h2u(a), h2u(b));
    }
}

// ---------------------------------------------------------------------------
// NT GEMM (fp16): C[M,N] = A[M,K] * B[N,K]^T, K contiguous halves.
// Tile 128x128, BK=32 halves, 3-stage cp.async ring (61,440 B dynamic smem).
// smem rows stored as half2 with stride BKP=20 words (80 B: 16B-multiple,
// and 20 mod 32 -> 20g+tig lane map is conflict-free, same family as the
// measured-good R7 layout).
// Warp 32x64 via 2x8 m16n8k16 tiles; fragment loads are single 32-bit LDS.
// MODE 0: A=g_X, B=g_Wqkv -> scatter g_Q / g_K / g_V(transposed), fp16
// MODE 3: A=g_O, B=g_Wout, +bias -> d_out fp32 (written from fp32 acc)
// ---------------------------------------------------------------------------
#define BKP 20                                   // half2 words per smem row
#define STAGE_U32 (2 * 128 * BKP)                // A + B per stage (words)
#define GEMM_SMEM_BYTES (3 * STAGE_U32 * 4)      // 61,440

template <int MODE>
__global__ __launch_bounds__(256, 2)
void gemm_nt(const float* __restrict__ bias, float* __restrict__ Cout, int K)
{
    extern __shared__ uint32_t sg[];

    const int tid  = threadIdx.x;
    const int lane = tid & 31;
    const int wid  = tid >> 5;
    const int g    = lane >> 2;
    const int tig  = lane & 3;
    const int wm   = wid & 3;
    const int wn   = wid >> 2;
    const int bm   = blockIdx.y;
    const int bn   = blockIdx.x;

    const __half* A = (MODE == 3) ? g_O : g_X;
    const __half* B = (MODE == 3) ? g_Wout : g_Wqkv;
    const __half* Arow = A + (size_t)(bm * 128) * K;
    const __half* Brow = B + (size_t)(bn * 128) * K;

    uint32_t sbase;
    asm("{ .reg .u64 t; cvta.to.shared.u64 t, %1; cvt.u32.u64 %0, t; }"
        : "=r"(sbase) : "l"(sg));

    float acc[2][8][4];
    #pragma unroll
    for (int mt = 0; mt < 2; mt++)
        #pragma unroll
        for (int nt = 0; nt < 8; nt++)
            #pragma unroll
            for (int i = 0; i < 4; i++) acc[mt][nt][i] = 0.f;

    const int KT = K / 32;

    // per stage per matrix: 128 rows x 4 chunks (8 halves each) = 512 chunks
    auto load_stage = [&](int s, int kt) {
        uint32_t stA = sbase + (uint32_t)s * STAGE_U32 * 4u;
        uint32_t stB = stA + 128u * BKP * 4u;
        #pragma unroll
        for (int i = 0; i < 2; i++) {
            int idx = i * 256 + tid;
            int row = idx >> 2, c4 = idx & 3;
            uint32_t so = (uint32_t)(row * BKP + c4 * 4) * 4u;
            const size_t go = (size_t)row * K + kt * 32 + c4 * 8;
            cp16s(stA + so, Arow + go);
            cp16s(stB + so, Brow + go);
        }
        CP_COMMIT();
    };

    load_stage(0, 0);
    load_stage(1, 1);

    int rbuf = 0;
    for (int kt = 0; kt < KT; kt++) {
        if (kt + 1 < KT) { CP_WAIT1(); } else { CP_WAIT0(); }
        __syncthreads();

        if (kt + 2 < KT) {
            int wbuf = rbuf + 2; if (wbuf >= 3) wbuf -= 3;
            load_stage(wbuf, kt + 2);
        }

        const uint32_t* As = sg + (size_t)rbuf * STAGE_U32;
        const uint32_t* Bs = As + 128 * BKP;
        #pragma unroll
        for (int ks = 0; ks < 2; ks++) {
            const int kc = ks * 8 + tig;            // half2 word within row
            uint32_t afr[2][4];
            #pragma unroll
            for (int mt = 0; mt < 2; mt++) {
                int r0 = wm * 32 + mt * 16 + g;
                afr[mt][0] = As[r0 * BKP + kc];
                afr[mt][1] = As[(r0 + 8) * BKP + kc];
                afr[mt][2] = As[r0 * BKP + kc + 4];
                afr[mt][3] = As[(r0 + 8) * BKP + kc + 4];
            }
            #pragma unroll
            for (int nt = 0; nt < 8; nt++) {
                int nr = wn * 64 + nt * 8 + g;
                uint32_t b0 = Bs[nr * BKP + kc];
                uint32_t b1 = Bs[nr * BKP + kc + 4];
                #pragma unroll
                for (int mt = 0; mt < 2; mt++)
                    mma_f16(acc[mt][nt], afr[mt], b0, b1);
            }
        }

        if (++rbuf == 3) rbuf = 0;
    }

    #pragma unroll
    for (int mt = 0; mt < 2; mt++) {
        #pragma unroll
        for (int nt = 0; nt < 8; nt++) {
            int row0 = bm * 128 + wm * 32 + mt * 16 + g;
            int col  = bn * 128 + wn * 64 + nt * 8 + 2 * tig;
            #pragma unroll
            for (int rr = 0; rr < 2; rr++) {
                int row = row0 + rr * 8;
                float x0 = acc[mt][nt][rr * 2 + 0];
                float x1 = acc[mt][nt][rr * 2 + 1];
                if (MODE == 0) {
                    int b = row >> 11, pos = row & 2047;
                    int which = col >> 11, rem = col & 2047;
                    int h = rem >> 7, d = rem & 127;
                    int bhh = (b << 4) + h;
                    if (which == 2) {
                        g_V[((size_t)bhh * DHEAD + d)     * SEQ + pos] = __float2half_rn(x0);
                        g_V[((size_t)bhh * DHEAD + d + 1) * SEQ + pos] = __float2half_rn(x1);
                    } else if (which == 0) {
                        *(__half2*)(g_Q + ((size_t)bhh * SEQ + pos) * DHEAD + d) =
                            __floats2half2_rn(x0, x1);
                    } else {
                        *(__half2*)(g_K + ((size_t)bhh * SEQ + pos) * DHEAD + d) =
                            __floats2half2_rn(x0, x1);
                    }
                } else {
                    *(float2*)(Cout + (size_t)row * DIM + col) =
                        make_float2(x0 + bias[col], x1 + bias[col + 1]);
                }
            }
        }
    }
}

// ---------------------------------------------------------------------------
// RoPE: in-place on fp16 g_Q, g_K (compute fp32, store fp16).
// ---------------------------------------------------------------------------
__global__ __launch_bounds__(256)
void rope_kernel()
{
    int t = blockIdx.x * blockDim.x + threadIdx.x;   // 64*2048*64 threads
    int i   = t & 63;
    int pos = (t >> 6) & 2047;
    int bh  = t >> 17;
    float p = (float)(2 * i) * (1.0f / 128.0f);
    float inv_freq = powf(10000.0f, -p);
    float fr = (float)pos * inv_freq;
    float s, c;
    sincosf(fr, &s, &c);
    size_t base = ((size_t)bh * SEQ + pos) * DHEAD;

    float q1 = __half2float(g_Q[base + i]), q2 = __half2float(g_Q[base + i + 64]);
    g_Q[base + i]      = __float2half_rn(q1 * c - q2 * s);
    g_Q[base + i + 64] = __float2half_rn(q2 * c + q1 * s);

    float k1 = __half2float(g_K[base + i]), k2 = __half2float(g_K[base + i + 64]);
    g_K[base + i]      = __float2half_rn(k1 * c - k2 * s);
    g_K[base + i + 64] = __float2half_rn(k2 * c + k1 * s);
}

// ---------------------------------------------------------------------------
// Fused flash attention (fp16 operands, fp32 softmax/accum).
// Block = (q-tile 128, bh); 8 warps x 16 q-rows; row reductions via
// shfl.bfly within 4-lane groups. Q register-resident fp16 fragments.
// K/V double-buffered cp.async; P fp16 through smem.
// smem strides (half2 words): K/Q rows 68, V/P rows 36 — conflict-free
// lane maps; row byte strides (272/144) are 16B multiples for cp.async.
// ---------------------------------------------------------------------------
#define TKV 64
#define NKVT (SEQ / TKV)     // 32
#define KSTH 68              // K/Q row stride (half2 words); 64 data + 4 pad
#define VSTH 36              // V/P row stride (half2 words); 32 data + 4 pad
// words: sK0 4352 | sK1 4352 | sV0 4608 | sV1 4608 | sP 4608 = 22528
#define FLASH_SMEM_BYTES (22528 * 4)   // 90,112

__global__ __launch_bounds__(256)
void flash_kernel()
{
    extern __shared__ uint32_t sm[];
    uint32_t* const sK0 = sm;
    uint32_t* const sK1 = sm + 4352;
    uint32_t* const sV0 = sm + 8704;
    uint32_t* const sV1 = sm + 13312;
    uint32_t* const sP  = sm + 17920;

    uint32_t sbase;
    asm("{ .reg .u64 t; cvta.to.shared.u64 t, %1; cvt.u32.u64 %0, t; }"
        : "=r"(sbase) : "l"(sm));

    const int tid  = threadIdx.x;
    const int lane = tid & 31;
    const int wid  = tid >> 5;
    const int g    = lane >> 2;
    const int tig  = lane & 3;
    const int bh   = blockIdx.y;
    const int q0   = blockIdx.x * 128;
    const float scale = 0.08838834764831845f;  // 128^-0.5

    const __half* Qg = g_Q + (size_t)bh * SEQ * DHEAD;
    const __half* Kg = g_K + (size_t)bh * SEQ * DHEAD;
    const __half* Vg = g_V + (size_t)bh * DHEAD * SEQ;

    // ---- stage Q tile (128 rows x 128 halves) into sm[0..8704) ----
    #pragma unroll
    for (int i = 0; i < 8; i++) {
        int e = i * 256 + tid;                 // 2048 chunks of 8 halves
        int row = e >> 4, c = e & 15;
        cp16s(sbase + (uint32_t)(row * KSTH + c * 4) * 4u,
              Qg + (size_t)(q0 + row) * DHEAD + c * 8);
    }
    CP_COMMIT();
    CP_WAIT0();
    __syncthreads();

    const int r0 = wid * 16 + g;               // first local q row
    uint32_t qf[8][4];
    #pragma unroll
    for (int ks = 0; ks < 8; ks++) {
        qf[ks][0] = sm[r0 * KSTH + ks * 8 + tig];
        qf[ks][1] = sm[(r0 + 8) * KSTH + ks * 8 + tig];
        qf[ks][2] = sm[r0 * KSTH + ks * 8 + tig + 4];
        qf[ks][3] = sm[(r0 + 8) * KSTH + ks * 8 + tig + 4];
    }
    __syncthreads();

    float oacc[16][4];
    #pragma unroll
    for (int nt = 0; nt < 16; nt++)
        #pragma unroll
        for (int i = 0; i < 4; i++) oacc[nt][i] = 0.f;
    float mrow0 = -1e30f, mrow1 = -1e30f;
    float lrow0 = 0.f, lrow1 = 0.f;

    // K/V tile loader: K = 64 rows x 16 chunks; V = 128 rows x 8 chunks
    auto load_kv = [&](uint32_t* dK, uint32_t* dV, int kv) {
        uint32_t aK = sbase + (uint32_t)(dK - sm) * 4u;
        uint32_t aV = sbase + (uint32_t)(dV - sm) * 4u;
        #pragma unroll
        for (int i = 0; i < 4; i++) {
            int e = i * 256 + tid;
            int kr = e >> 4, kc = e & 15;
            cp16s(aK + (uint32_t)(kr * KSTH + kc * 4) * 4u,
                  Kg + (size_t)(kv + kr) * DHEAD + kc * 8);
        }
        #pragma unroll
        for (int i = 0; i < 4; i++) {
            int e = i * 256 + tid;
            int vr = e >> 3, vc = e & 7;
            cp16s(aV + (uint32_t)(vr * VSTH + vc * 4) * 4u,
                  Vg + (size_t)vr * SEQ + kv + vc * 8);
        }
        CP_COMMIT();
    };

    load_kv(sK0, sV0, 0);

    for (int it = 0; it < NKVT; it++) {
        const int buf = it & 1;
        const uint32_t* sK = buf ? sK1 : sK0;
        const uint32_t* sV = buf ? sV1 : sV0;

        if (it + 1 < NKVT) {
            load_kv(buf ? sK0 : sK1, buf ? sV0 : sV1, (it + 1) * TKV);
            CP_WAIT1();
        } else {
            CP_WAIT0();
        }
        __syncthreads();

        // ---- S = Q K^T : 16 q rows x 64 kv cols per warp (64 MMAs) ----
        float sacc[8][4];
        #pragma unroll
        for (int nt = 0; nt < 8; nt++)
            #pragma unroll
            for (int i = 0; i < 4; i++) sacc[nt][i] = 0.f;

        #pragma unroll
        for (int ks = 0; ks < 8; ks++) {
            #pragma unroll
            for (int nt = 0; nt < 8; nt++) {
                uint32_t b0 = sK[(nt * 8 + g) * KSTH + ks * 8 + tig];
                uint32_t b1 = sK[(nt * 8 + g) * KSTH + ks * 8 + tig + 4];
                mma_f16(sacc[nt], qf[ks], b0, b1);
            }
        }

        // ---- online softmax (rows r0, r0+8) ----
        float tm0 = -1e30f, tm1 = -1e30f;
        #pragma unroll
        for (int nt = 0; nt < 8; nt++) {
            tm0 = fmaxf(tm0, fmaxf(sacc[nt][0], sacc[nt][1]));
            tm1 = fmaxf(tm1, fmaxf(sacc[nt][2], sacc[nt][3]));
        }
        tm0 = fmaxf(tm0, __shfl_xor_sync(0xffffffffu, tm0, 1));
        tm0 = fmaxf(tm0, __shfl_xor_sync(0xffffffffu, tm0, 2));
        tm1 = fmaxf(tm1, __shfl_xor_sync(0xffffffffu, tm1, 1));
        tm1 = fmaxf(tm1, __shfl_xor_sync(0xffffffffu, tm1, 2));

        float mn0 = fmaxf(mrow0, tm0 * scale);
        float mn1 = fmaxf(mrow1, tm1 * scale);
        float sf0 = __expf(mrow0 - mn0);
        float sf1 = __expf(mrow1 - mn1);
        mrow0 = mn0; mrow1 = mn1;

        float rs0 = 0.f, rs1 = 0.f;
        #pragma unroll
        for (int nt = 0; nt < 8; nt++) {
            float p0 = __expf(sacc[nt][0] * scale - mn0);
            float p1 = __expf(sacc[nt][1] * scale - mn0);
            float p2 = __expf(sacc[nt][2] * scale - mn1);
            float p3 = __expf(sacc[nt][3] * scale - mn1);
            rs0 += p0 + p1;
            rs1 += p2 + p3;
            sP[r0 * VSTH + nt * 4 + tig]       = h2u(__floats2half2_rn(p0, p1));
            sP[(r0 + 8) * VSTH + nt * 4 + tig] = h2u(__floats2half2_rn(p2, p3));
        }
        rs0 += __shfl_xor_sync(0xffffffffu, rs0, 1);
        rs0 += __shfl_xor_sync(0xffffffffu, rs0, 2);
        rs1 += __shfl_xor_sync(0xffffffffu, rs1, 1);
        rs1 += __shfl_xor_sync(0xffffffffu, rs1, 2);
        lrow0 = lrow0 * sf0 + rs0;
        lrow1 = lrow1 * sf1 + rs1;

        #pragma unroll
        for (int nt = 0; nt < 16; nt++) {
            oacc[nt][0] *= sf0;
            oacc[nt][1] *= sf0;
            oacc[nt][2] *= sf1;
            oacc[nt][3] *= sf1;
        }
        __syncthreads();   // sP visible to all

        // ---- O += P V  (4 ksteps x 16 nt = 64 MMAs) ----
        #pragma unroll
        for (int ks = 0; ks < 4; ks++) {
            uint32_t afr[4];
            afr[0] = sP[r0 * VSTH + ks * 8 + tig];
            afr[1] = sP[(r0 + 8) * VSTH + ks * 8 + tig];
            afr[2] = sP[r0 * VSTH + ks * 8 + tig + 4];
            afr[3] = sP[(r0 + 8) * VSTH + ks * 8 + tig + 4];
            #pragma unroll
            for (int nt = 0; nt < 16; nt++) {
                uint32_t b0 = sV[(nt * 8 + g) * VSTH + ks * 8 + tig];
                uint32_t b1 = sV[(nt * 8 + g) * VSTH + ks * 8 + tig + 4];
                mma_f16(oacc[nt], afr, b0, b1);
            }
        }
        __syncthreads();
    }

    // ---- epilogue: normalize, write fp16 g_O ----
    float inv0 = 1.f / lrow0;
    float inv1 = 1.f / lrow1;
    int b = bh >> 4, h = bh & 15;
    __half* Og = g_O + ((size_t)(b * SEQ + q0)) * DIM + h * DHEAD;
    #pragma unroll
    for (int nt = 0; nt < 16; nt++) {
        int col = nt * 8 + 2 * tig;
        *(__half2*)(Og + (size_t)r0 * DIM + col) =
            __floats2half2_rn(oacc[nt][0] * inv0, oacc[nt][1] * inv0);
        *(__half2*)(Og + (size_t)(r0 + 8) * DIM + col) =
            __floats2half2_rn(oacc[nt][2] * inv1, oacc[nt][3] * inv1);
    }
}

// ---------------------------------------------------------------------------
// Launch: metadata order = x, w_qkv, w_out, b_out ; output fp32 [4,2048,2048]
// No static state: attributes set unconditionally (idempotent, capture-safe).
// ---------------------------------------------------------------------------
extern "C" void kernel_launch(void* const* d_in, const int* in_sizes, int n_in,
                              void* d_out, int out_size)
{
    const float* x     = (const float*)d_in[0];
    const float* w_qkv = (const float*)d_in[1];
    const float* w_out = (const float*)d_in[2];
    const float* b_out = (const float*)d_in[3];
    float* out = (float*)d_out;

    cudaFuncSetAttribute(flash_kernel,
                         cudaFuncAttributeMaxDynamicSharedMemorySize,
                         FLASH_SMEM_BYTES);
    cudaFuncSetAttribute(gemm_nt<0>,
                         cudaFuncAttributeMaxDynamicSharedMemorySize,
                         GEMM_SMEM_BYTES);
    cudaFuncSetAttribute(gemm_nt<3>,
                         cudaFuncAttributeMaxDynamicSharedMemorySize,
                         GEMM_SMEM_BYTES);

    __half* gx; __half* gwq; __half* gwo;
    cudaGetSymbolAddress((void**)&gx,  g_X);
    cudaGetSymbolAddress((void**)&gwq, g_Wqkv);
    cudaGetSymbolAddress((void**)&gwo, g_Wout);

    // Prepass: fp16-round inputs (single rounding point per operand).
    const int n4x = (BATCH * SEQ * DIM) / 4;
    const int n4q = (3 * DIM * DIM) / 4;
    const int n4o = (DIM * DIM) / 4;
    round_half<<<(n4x + 255) / 256, 256>>>((const float4*)x,     (uint2*)gx,  n4x);
    round_half<<<(n4q + 255) / 256, 256>>>((const float4*)w_qkv, (uint2*)gwq, n4q);
    round_half<<<(n4o + 255) / 256, 256>>>((const float4*)w_out, (uint2*)gwo, n4o);

    // QKV projection: [8192,2048] x [6144,2048]^T -> Q/K/V fp16 layouts
    gemm_nt<0><<<dim3(48, 64, 1), 256, GEMM_SMEM_BYTES>>>(nullptr, nullptr, 2048);
    // RoPE in place on Q, K
    rope_kernel<<<(BHTOT * SEQ * 64) / 256, 256>>>();
    // Fused attention -> g_O (fp16)
    flash_kernel<<<dim3(16, 64, 1), 256, FLASH_SMEM_BYTES>>>();
    // Output projection + bias: [8192,2048] x [2048,2048]^T -> fp32 out
    gemm_nt<3><<<dim3(16, 64, 1), 256, GEMM_SMEM_BYTES>>>(b_out, out, 2048);
}

// round 13
// speedup vs baseline: 2.6518x; 1.0802x over previous
#include <cuda_runtime.h>
#include <cuda_fp16.h>
#include <cstdint>

// Problem constants
#define NHEADS 16
#define DHEAD  128
#define SEQ    2048
#define BATCH  4
#define DIM    2048
#define BHTOT  (BATCH * NHEADS)   // 64

// NOTE (R9 lesson): harness compiles with -arch=sm_100 (no 'a' suffix) —
// tcgen05/TMEM are NOT available. Legacy mma.sync + ldmatrix only.

// Scratch (device globals: allocation-free per harness rules) — fp16 operands
__device__ __half g_Q[(size_t)BHTOT * SEQ * DHEAD];     // [bh][n][d]
__device__ __half g_K[(size_t)BHTOT * SEQ * DHEAD];     // [bh][n][d]
__device__ __half g_V[(size_t)BHTOT * DHEAD * SEQ];     // [bh][d][n] transposed
__device__ __half g_O[(size_t)BATCH * SEQ * DIM];       // [b][n][h*d]
__device__ __half g_X[(size_t)BATCH * SEQ * DIM];       // fp16 copy of x
__device__ __half g_Wqkv[(size_t)3 * DIM * DIM];        // fp16 copy of w_qkv
__device__ __half g_Wout[(size_t)DIM * DIM];            // fp16 copy of w_out

// ---------------------------------------------------------------------------
// Helpers
// ---------------------------------------------------------------------------
__device__ __forceinline__ void mma_f16(float* c, const uint32_t* a, uint32_t b0, uint32_t b1) {
    asm volatile(
        "mma.sync.aligned.m16n8k16.row.col.f32.f16.f16.f32 "
        "{%0,%1,%2,%3}, {%4,%5,%6,%7}, {%8,%9}, {%0,%1,%2,%3};\n"
        : "+f"(c[0]), "+f"(c[1]), "+f"(c[2]), "+f"(c[3])
        : "r"(a[0]), "r"(a[1]), "r"(a[2]), "r"(a[3]), "r"(b0), "r"(b1));
}

// ldmatrix x4: four 8x8 b16 matrices; lane l of matrix m gets (l/4, 2(l%4)).
__device__ __forceinline__ void ldsm_x4(uint32_t* r, uint32_t addr) {
    asm volatile("ldmatrix.sync.aligned.m8n8.x4.shared.b16 {%0,%1,%2,%3}, [%4];"
        : "=r"(r[0]), "=r"(r[1]), "=r"(r[2]), "=r"(r[3]) : "r"(addr));
}

__device__ __forceinline__ void cp16s(uint32_t sa, const void* g) {
    asm volatile("cp.async.cg.shared.global [%0], [%1], 16;\n" :: "r"(sa), "l"(g));
}
#define CP_COMMIT() asm volatile("cp.async.commit_group;\n" ::: "memory")
#define CP_WAIT1()  asm volatile("cp.async.wait_group 1;\n" ::: "memory")
#define CP_WAIT0()  asm volatile("cp.async.wait_group 0;\n" ::: "memory")

__device__ __forceinline__ uint32_t h2u(__half2 h) { return *(uint32_t*)&h; }

// ---------------------------------------------------------------------------
// Prepass: fp32 -> fp16 (RN), float4 -> 4 halves (uint2).
// ---------------------------------------------------------------------------
__global__ __launch_bounds__(256)
void round_half(const float4* __restrict__ src, uint2* __restrict__ dst, int n4)
{
    int i = blockIdx.x * blockDim.x + threadIdx.x;
    if (i < n4) {
        float4 v = src[i];
        __half2 a = __floats2half2_rn(v.x, v.y);
        __half2 b = __floats2half2_rn(v.z, v.w);
        dst[i] = make_uint2(h2u(a), h2u(b));
    }
}

// ---------------------------------------------------------------------------
// NT GEMM (fp16): C[M,N] = A[M,K] * B[N,K]^T, K contiguous halves.
// Tile 128x128, BK=32 halves, 3-stage cp.async ring (61,440 B dynamic smem).
// smem rows: half2 words, stride BKP=20 (80 B). 80·r mod 128 covers all 8
// 16B columns across any 8 consecutive rows -> ldmatrix phases conflict-free.
// Fragments via ldmatrix.x4: A tiles (16x16) and B tile-pairs (2 x n8k16).
// MODE 0: A=g_X, B=g_Wqkv -> scatter g_Q / g_K / g_V(transposed), fp16
// MODE 3: A=g_O, B=g_Wout, +bias -> d_out fp32 (written from fp32 acc)
// ---------------------------------------------------------------------------
#define BKP 20                                   // half2 words per smem row
#define STAGE_U32 (2 * 128 * BKP)                // A + B per stage (words)
#define GEMM_SMEM_BYTES (3 * STAGE_U32 * 4)      // 61,440

template <int MODE>
__global__ __launch_bounds__(256, 2)
void gemm_nt(const float* __restrict__ bias, float* __restrict__ Cout, int K)
{
    extern __shared__ uint32_t sg[];

    const int tid  = threadIdx.x;
    const int lane = tid & 31;
    const int wid  = tid >> 5;
    const int g    = lane >> 2;
    const int tig  = lane & 3;
    const int wm   = wid & 3;
    const int wn   = wid >> 2;
    const int bm   = blockIdx.y;
    const int bn   = blockIdx.x;

    // ldmatrix per-lane offsets
    const int lr8   = lane & 7;
    const int arow  = lr8 + ((lane & 8)  ? 8 : 0);   // A-type: rows split by bit3
    const int acolw = (lane & 16) ? 4 : 0;           //         k split by bit4
    const int brow  = lr8 + ((lane & 16) ? 8 : 0);   // B-type: rows split by bit4
    const int bcolw = (lane & 8)  ? 4 : 0;           //         k split by bit3

    const __half* A = (MODE == 3) ? g_O : g_X;
    const __half* B = (MODE == 3) ? g_Wout : g_Wqkv;
    const __half* Arow_g = A + (size_t)(bm * 128) * K;
    const __half* Brow_g = B + (size_t)(bn * 128) * K;

    uint32_t sbase;
    asm("{ .reg .u64 t; cvta.to.shared.u64 t, %1; cvt.u32.u64 %0, t; }"
        : "=r"(sbase) : "l"(sg));

    float acc[2][8][4];
    #pragma unroll
    for (int mt = 0; mt < 2; mt++)
        #pragma unroll
        for (int nt = 0; nt < 8; nt++)
            #pragma unroll
            for (int i = 0; i < 4; i++) acc[mt][nt][i] = 0.f;

    const int KT = K / 32;

    auto load_stage = [&](int s, int kt) {
        uint32_t stA = sbase + (uint32_t)s * STAGE_U32 * 4u;
        uint32_t stB = stA + 128u * BKP * 4u;
        #pragma unroll
        for (int i = 0; i < 2; i++) {
            int idx = i * 256 + tid;
            int row = idx >> 2, c4 = idx & 3;
            uint32_t so = (uint32_t)(row * BKP + c4 * 4) * 4u;
            const size_t go = (size_t)row * K + kt * 32 + c4 * 8;
            cp16s(stA + so, Arow_g + go);
            cp16s(stB + so, Brow_g + go);
        }
        CP_COMMIT();
    };

    load_stage(0, 0);
    load_stage(1, 1);

    int rbuf = 0;
    for (int kt = 0; kt < KT; kt++) {
        if (kt + 1 < KT) { CP_WAIT1(); } else { CP_WAIT0(); }
        __syncthreads();

        if (kt + 2 < KT) {
            int wbuf = rbuf + 2; if (wbuf >= 3) wbuf -= 3;
            load_stage(wbuf, kt + 2);
        }

        const uint32_t aA = sbase + (uint32_t)rbuf * STAGE_U32 * 4u;
        const uint32_t aB = aA + 128u * BKP * 4u;
        #pragma unroll
        for (int ks = 0; ks < 2; ks++) {
            uint32_t afr[2][4];
            #pragma unroll
            for (int mt = 0; mt < 2; mt++) {
                int row = wm * 32 + mt * 16 + arow;
                ldsm_x4(afr[mt], aA + (uint32_t)(row * BKP + ks * 8 + acolw) * 4u);
            }
            #pragma unroll
            for (int ntp = 0; ntp < 4; ntp++) {
                int nrow = wn * 64 + ntp * 16 + brow;
                uint32_t bfr[4];
                ldsm_x4(bfr, aB + (uint32_t)(nrow * BKP + ks * 8 + bcolw) * 4u);
                #pragma unroll
                for (int mt = 0; mt < 2; mt++) {
                    mma_f16(acc[mt][2 * ntp],     afr[mt], bfr[0], bfr[1]);
                    mma_f16(acc[mt][2 * ntp + 1], afr[mt], bfr[2], bfr[3]);
                }
            }
        }

        if (++rbuf == 3) rbuf = 0;
    }

    #pragma unroll
    for (int mt = 0; mt < 2; mt++) {
        #pragma unroll
        for (int nt = 0; nt < 8; nt++) {
            int row0 = bm * 128 + wm * 32 + mt * 16 + g;
            int col  = bn * 128 + wn * 64 + nt * 8 + 2 * tig;
            #pragma unroll
            for (int rr = 0; rr < 2; rr++) {
                int row = row0 + rr * 8;
                float x0 = acc[mt][nt][rr * 2 + 0];
                float x1 = acc[mt][nt][rr * 2 + 1];
                if (MODE == 0) {
                    int b = row >> 11, pos = row & 2047;
                    int which = col >> 11, rem = col & 2047;
                    int h = rem >> 7, d = rem & 127;
                    int bhh = (b << 4) + h;
                    if (which == 2) {
                        g_V[((size_t)bhh * DHEAD + d)     * SEQ + pos] = __float2half_rn(x0);
                        g_V[((size_t)bhh * DHEAD + d + 1) * SEQ + pos] = __float2half_rn(x1);
                    } else if (which == 0) {
                        *(__half2*)(g_Q + ((size_t)bhh * SEQ + pos) * DHEAD + d) =
                            __floats2half2_rn(x0, x1);
                    } else {
                        *(__half2*)(g_K + ((size_t)bhh * SEQ + pos) * DHEAD + d) =
                            __floats2half2_rn(x0, x1);
                    }
                } else {
                    *(float2*)(Cout + (size_t)row * DIM + col) =
                        make_float2(x0 + bias[col], x1 + bias[col + 1]);
                }
            }
        }
    }
}

// ---------------------------------------------------------------------------
// RoPE: in-place on fp16 g_Q, g_K (compute fp32, store fp16).
// ---------------------------------------------------------------------------
__global__ __launch_bounds__(256)
void rope_kernel()
{
    int t = blockIdx.x * blockDim.x + threadIdx.x;   // 64*2048*64 threads
    int i   = t & 63;
    int pos = (t >> 6) & 2047;
    int bh  = t >> 17;
    float p = (float)(2 * i) * (1.0f / 128.0f);
    float inv_freq = powf(10000.0f, -p);
    float fr = (float)pos * inv_freq;
    float s, c;
    sincosf(fr, &s, &c);
    size_t base = ((size_t)bh * SEQ + pos) * DHEAD;

    float q1 = __half2float(g_Q[base + i]), q2 = __half2float(g_Q[base + i + 64]);
    g_Q[base + i]      = __float2half_rn(q1 * c - q2 * s);
    g_Q[base + i + 64] = __float2half_rn(q2 * c + q1 * s);

    float k1 = __half2float(g_K[base + i]), k2 = __half2float(g_K[base + i + 64]);
    g_K[base + i]      = __float2half_rn(k1 * c - k2 * s);
    g_K[base + i + 64] = __float2half_rn(k2 * c + k1 * s);
}

// ---------------------------------------------------------------------------
// Fused flash attention (fp16 operands, fp32 softmax/accum), ldmatrix loads.
// Block = (q-tile 128, bh); 8 warps x 16 q-rows; row reductions via
// shfl.bfly within 4-lane groups. Q fragments via ldmatrix (once).
// K/V double-buffered cp.async; P fp16 through smem.
// Row strides 272 B (K/Q) and 144 B (V/P): 16·r mod 128 distinct per 8 rows
// -> ldmatrix conflict-free; 16B multiples for cp.async.
// ---------------------------------------------------------------------------
#define TKV 64
#define NKVT (SEQ / TKV)     // 32
#define KSTH 68              // K/Q row stride (half2 words)
#define VSTH 36              // V/P row stride (half2 words)
// words: sK0 4352 | sK1 4352 | sV0 4608 | sV1 4608 | sP 4608 = 22528
#define FLASH_SMEM_BYTES (22528 * 4)   // 90,112

__global__ __launch_bounds__(256)
void flash_kernel()
{
    extern __shared__ uint32_t sm[];
    uint32_t* const sK0 = sm;
    uint32_t* const sK1 = sm + 4352;
    uint32_t* const sV0 = sm + 8704;
    uint32_t* const sV1 = sm + 13312;
    uint32_t* const sP  = sm + 17920;

    uint32_t sbase;
    asm("{ .reg .u64 t; cvta.to.shared.u64 t, %1; cvt.u32.u64 %0, t; }"
        : "=r"(sbase) : "l"(sm));

    const int tid  = threadIdx.x;
    const int lane = tid & 31;
    const int wid  = tid >> 5;
    const int g    = lane >> 2;
    const int tig  = lane & 3;
    const int bh   = blockIdx.y;
    const int q0   = blockIdx.x * 128;
    const float scale = 0.08838834764831845f;  // 128^-0.5

    // ldmatrix per-lane offsets (same mapping as gemm)
    const int lr8   = lane & 7;
    const int arow  = lr8 + ((lane & 8)  ? 8 : 0);
    const int acolw = (lane & 16) ? 4 : 0;
    const int brow  = lr8 + ((lane & 16) ? 8 : 0);
    const int bcolw = (lane & 8)  ? 4 : 0;

    const __half* Qg = g_Q + (size_t)bh * SEQ * DHEAD;
    const __half* Kg = g_K + (size_t)bh * SEQ * DHEAD;
    const __half* Vg = g_V + (size_t)bh * DHEAD * SEQ;

    // ---- stage Q tile (128 rows x 128 halves) into sm[0..8704) ----
    #pragma unroll
    for (int i = 0; i < 8; i++) {
        int e = i * 256 + tid;                 // 2048 chunks of 8 halves
        int row = e >> 4, c = e & 15;
        cp16s(sbase + (uint32_t)(row * KSTH + c * 4) * 4u,
              Qg + (size_t)(q0 + row) * DHEAD + c * 8);
    }
    CP_COMMIT();
    CP_WAIT0();
    __syncthreads();

    const int r0 = wid * 16 + g;               // first local q row (epilogue)
    uint32_t qf[8][4];
    #pragma unroll
    for (int ks = 0; ks < 8; ks++) {
        int row = wid * 16 + arow;
        ldsm_x4(qf[ks], sbase + (uint32_t)(row * KSTH + ks * 8 + acolw) * 4u);
    }
    __syncthreads();

    float oacc[16][4];
    #pragma unroll
    for (int nt = 0; nt < 16; nt++)
        #pragma unroll
        for (int i = 0; i < 4; i++) oacc[nt][i] = 0.f;
    float mrow0 = -1e30f, mrow1 = -1e30f;
    float lrow0 = 0.f, lrow1 = 0.f;

    auto load_kv = [&](uint32_t* dK, uint32_t* dV, int kv) {
        uint32_t aK = sbase + (uint32_t)(dK - sm) * 4u;
        uint32_t aV = sbase + (uint32_t)(dV - sm) * 4u;
        #pragma unroll
        for (int i = 0; i < 4; i++) {
            int e = i * 256 + tid;
            int kr = e >> 4, kc = e & 15;
            cp16s(aK + (uint32_t)(kr * KSTH + kc * 4) * 4u,
                  Kg + (size_t)(kv + kr) * DHEAD + kc * 8);
        }
        #pragma unroll
        for (int i = 0; i < 4; i++) {
            int e = i * 256 + tid;
            int vr = e >> 3, vc = e & 7;
            cp16s(aV + (uint32_t)(vr * VSTH + vc * 4) * 4u,
                  Vg + (size_t)vr * SEQ + kv + vc * 8);
        }
        CP_COMMIT();
    };

    load_kv(sK0, sV0, 0);

    const uint32_t aP = sbase + (uint32_t)(sP - sm) * 4u;

    for (int it = 0; it < NKVT; it++) {
        const int buf = it & 1;
        const uint32_t aK = sbase + (uint32_t)((buf ? sK1 : sK0) - sm) * 4u;
        const uint32_t aV = sbase + (uint32_t)((buf ? sV1 : sV0) - sm) * 4u;

        if (it + 1 < NKVT) {
            load_kv(buf ? sK0 : sK1, buf ? sV0 : sV1, (it + 1) * TKV);
            CP_WAIT1();
        } else {
            CP_WAIT0();
        }
        __syncthreads();

        // ---- S = Q K^T : 16 q rows x 64 kv cols per warp ----
        float sacc[8][4];
        #pragma unroll
        for (int nt = 0; nt < 8; nt++)
            #pragma unroll
            for (int i = 0; i < 4; i++) sacc[nt][i] = 0.f;

        #pragma unroll
        for (int ks = 0; ks < 8; ks++) {
            #pragma unroll
            for (int ntp = 0; ntp < 4; ntp++) {
                int nrow = ntp * 16 + brow;
                uint32_t bfr[4];
                ldsm_x4(bfr, aK + (uint32_t)(nrow * KSTH + ks * 8 + bcolw) * 4u);
                mma_f16(sacc[2 * ntp],     qf[ks], bfr[0], bfr[1]);
                mma_f16(sacc[2 * ntp + 1], qf[ks], bfr[2], bfr[3]);
            }
        }

        // ---- online softmax (rows r0, r0+8) ----
        float tm0 = -1e30f, tm1 = -1e30f;
        #pragma unroll
        for (int nt = 0; nt < 8; nt++) {
            tm0 = fmaxf(tm0, fmaxf(sacc[nt][0], sacc[nt][1]));
            tm1 = fmaxf(tm1, fmaxf(sacc[nt][2], sacc[nt][3]));
        }
        tm0 = fmaxf(tm0, __shfl_xor_sync(0xffffffffu, tm0, 1));
        tm0 = fmaxf(tm0, __shfl_xor_sync(0xffffffffu, tm0, 2));
        tm1 = fmaxf(tm1, __shfl_xor_sync(0xffffffffu, tm1, 1));
        tm1 = fmaxf(tm1, __shfl_xor_sync(0xffffffffu, tm1, 2));

        float mn0 = fmaxf(mrow0, tm0 * scale);
        float mn1 = fmaxf(mrow1, tm1 * scale);
        float sf0 = __expf(mrow0 - mn0);
        float sf1 = __expf(mrow1 - mn1);
        mrow0 = mn0; mrow1 = mn1;

        float rs0 = 0.f, rs1 = 0.f;
        #pragma unroll
        for (int nt = 0; nt < 8; nt++) {
            float p0 = __expf(sacc[nt][0] * scale - mn0);
            float p1 = __expf(sacc[nt][1] * scale - mn0);
            float p2 = __expf(sacc[nt][2] * scale - mn1);
            float p3 = __expf(sacc[nt][3] * scale - mn1);
            rs0 += p0 + p1;
            rs1 += p2 + p3;
            sP[r0 * VSTH + nt * 4 + tig]       = h2u(__floats2half2_rn(p0, p1));
            sP[(r0 + 8) * VSTH + nt * 4 + tig] = h2u(__floats2half2_rn(p2, p3));
        }
        rs0 += __shfl_xor_sync(0xffffffffu, rs0, 1);
        rs0 += __shfl_xor_sync(0xffffffffu, rs0, 2);
        rs1 += __shfl_xor_sync(0xffffffffu, rs1, 1);
        rs1 += __shfl_xor_sync(0xffffffffu, rs1, 2);
        lrow0 = lrow0 * sf0 + rs0;
        lrow1 = lrow1 * sf1 + rs1;

        #pragma unroll
        for (int nt = 0; nt < 16; nt++) {
            oacc[nt][0] *= sf0;
            oacc[nt][1] *= sf0;
            oacc[nt][2] *= sf1;
            oacc[nt][3] *= sf1;
        }
        __syncthreads();   // sP visible to all

        // ---- O += P V ----
        #pragma unroll
        for (int ks = 0; ks < 4; ks++) {
            uint32_t afr[4];
            int prow = wid * 16 + arow;
            ldsm_x4(afr, aP + (uint32_t)(prow * VSTH + ks * 8 + acolw) * 4u);
            #pragma unroll
            for (int ntp = 0; ntp < 8; ntp++) {
                int vrow = ntp * 16 + brow;
                uint32_t bfr[4];
                ldsm_x4(bfr, aV + (uint32_t)(vrow * VSTH + ks * 8 + bcolw) * 4u);
                mma_f16(oacc[2 * ntp],     afr, bfr[0], bfr[1]);
                mma_f16(oacc[2 * ntp + 1], afr, bfr[2], bfr[3]);
            }
        }
        __syncthreads();
    }

    // ---- epilogue: normalize, write fp16 g_O ----
    float inv0 = 1.f / lrow0;
    float inv1 = 1.f / lrow1;
    int b = bh >> 4, h = bh & 15;
    __half* Og = g_O + ((size_t)(b * SEQ + q0)) * DIM + h * DHEAD;
    #pragma unroll
    for (int nt = 0; nt < 16; nt++) {
        int col = nt * 8 + 2 * tig;
        *(__half2*)(Og + (size_t)r0 * DIM + col) =
            __floats2half2_rn(oacc[nt][0] * inv0, oacc[nt][1] * inv0);
        *(__half2*)(Og + (size_t)(r0 + 8) * DIM + col) =
            __floats2half2_rn(oacc[nt][2] * inv1, oacc[nt][3] * inv1);
    }
}

// ---------------------------------------------------------------------------
// Launch: metadata order = x, w_qkv, w_out, b_out ; output fp32 [4,2048,2048]
// No static state: attributes set unconditionally (idempotent, capture-safe).
// ---------------------------------------------------------------------------
extern "C" void kernel_launch(void* const* d_in, const int* in_sizes, int n_in,
                              void* d_out, int out_size)
{
    const float* x     = (const float*)d_in[0];
    const float* w_qkv = (const float*)d_in[1];
    const float* w_out = (const float*)d_in[2];
    const float* b_out = (const float*)d_in[3];
    float* out = (float*)d_out;

    cudaFuncSetAttribute(flash_kernel,
                         cudaFuncAttributeMaxDynamicSharedMemorySize,
                         FLASH_SMEM_BYTES);
    cudaFuncSetAttribute(gemm_nt<0>,
                         cudaFuncAttributeMaxDynamicSharedMemorySize,
                         GEMM_SMEM_BYTES);
    cudaFuncSetAttribute(gemm_nt<3>,
                         cudaFuncAttributeMaxDynamicSharedMemorySize,
                         GEMM_SMEM_BYTES);

    __half* gx; __half* gwq; __half* gwo;
    cudaGetSymbolAddress((void**)&gx,  g_X);
    cudaGetSymbolAddress((void**)&gwq, g_Wqkv);
    cudaGetSymbolAddress((void**)&gwo, g_Wout);

    // Prepass: fp16-round inputs (single rounding point per operand).
    const int n4x = (BATCH * SEQ * DIM) / 4;
    const int n4q = (3 * DIM * DIM) / 4;
    const int n4o = (DIM * DIM) / 4;
    round_half<<<(n4x + 255) / 256, 256>>>((const float4*)x,     (uint2*)gx,  n4x);
    round_half<<<(n4q + 255) / 256, 256>>>((const float4*)w_qkv, (uint2*)gwq, n4q);
    round_half<<<(n4o + 255) / 256, 256>>>((const float4*)w_out, (uint2*)gwo, n4o);

    // QKV projection: [8192,2048] x [6144,2048]^T -> Q/K/V fp16 layouts
    gemm_nt<0><<<dim3(48, 64, 1), 256, GEMM_SMEM_BYTES>>>(nullptr, nullptr, 2048);
    // RoPE in place on Q, K
    rope_kernel<<<(BHTOT * SEQ * 64) / 256, 256>>>();
    // Fused attention -> g_O (fp16)
    flash_kernel<<<dim3(16, 64, 1), 256, FLASH_SMEM_BYTES>>>();
    // Output projection + bias: [8192,2048] x [2048,2048]^T -> fp32 out
    gemm_nt<3><<<dim3(16, 64, 1), 256, GEMM_SMEM_BYTES>>>(b_out, out, 2048);
}